// round 12
// baseline (speedup 1.0000x reference)
#include <cuda_runtime.h>
#include <cuda_bf16.h>
#include <cstdint>

// Sparsemax along last dim (n = 512) of a (64, 1024, 512) fp32 tensor.
// Two rows per warp, 16 elements/lane/row in registers.
//
// tau* >= max(z) - 1, so the support is a subset of {z > max-1} (~7 elems
// for N(0,1)). Candidates are compacted to 2 regs/lane; Michelot's
// iteration runs on the compacted set (exact). The two rows' warp
// reduction ladders are hand-interleaved so their SHFL chains pipeline,
// halving the exposed serial latency that bounds this kernel.

#define ROW_N   512
#define ELEMS   16
#define WARPS_PER_BLOCK 8
#define THREADS (WARPS_PER_BLOCK * 32)
#define FULLM   0xFFFFFFFFu

__device__ __forceinline__ void warp_sum2(float& a, float& b) {
    #pragma unroll
    for (int m = 16; m > 0; m >>= 1) {
        a += __shfl_xor_sync(FULLM, a, m);
        b += __shfl_xor_sync(FULLM, b, m);
    }
}

__device__ __forceinline__ void warp_max2(float& a, float& b) {
    #pragma unroll
    for (int m = 16; m > 0; m >>= 1) {
        a = fmaxf(a, __shfl_xor_sync(FULLM, a, m));
        b = fmaxf(b, __shfl_xor_sync(FULLM, b, m));
    }
}

__device__ __forceinline__ float warp_sum(float v) {
    #pragma unroll
    for (int m = 16; m > 0; m >>= 1)
        v += __shfl_xor_sync(FULLM, v, m);
    return v;
}

// Rare fallback: full 16-element Michelot for a row whose candidate set
// exceeds 2 per lane somewhere. Warp-uniform call.
__device__ __noinline__ float solve_full(const float z[ELEMS], float thr) {
    float ps = 0.0f;
    int   pc = 0;
    #pragma unroll
    for (int i = 0; i < ELEMS; i++) {
        bool g = z[i] > thr;
        ps += g ? z[i] : 0.0f;
        pc += g ? 1 : 0;
    }
    ps = warp_sum(ps);
    pc = __reduce_add_sync(FULLM, pc);
    float tau = __fdividef(ps - 1.0f, (float)pc);
    int   cnt = pc;
    #pragma unroll 1
    for (int it = 0; it < 48; it++) {
        float s = 0.0f;
        int   c = 0;
        #pragma unroll
        for (int i = 0; i < ELEMS; i++) {
            bool g = z[i] > tau;
            s += g ? z[i] : 0.0f;
            c += g ? 1 : 0;
        }
        s = warp_sum(s);
        c = __reduce_add_sync(FULLM, c);
        if (c == cnt) break;
        cnt = c;
        tau = __fdividef(s - 1.0f, (float)c);
    }
    return tau;
}

__global__ __launch_bounds__(THREADS)
void sparsemax_kernel(const float* __restrict__ x,
                      float* __restrict__ out,
                      int rows) {
    const int pair = blockIdx.x * WARPS_PER_BLOCK + (threadIdx.x >> 5);
    const int lane = threadIdx.x & 31;
    int row0 = pair * 2;
    if (row0 >= rows) return;
    int row1 = (row0 + 1 < rows) ? row0 + 1 : row0;

    const float4* __restrict__ x0 =
        reinterpret_cast<const float4*>(x + (size_t)row0 * ROW_N);
    const float4* __restrict__ x1 =
        reinterpret_cast<const float4*>(x + (size_t)row1 * ROW_N);

    // Front-batch all 8 float4 loads (MLP = 8).
    float4 r0[4], r1[4];
    #pragma unroll
    for (int j = 0; j < 4; j++) r0[j] = x0[lane + 32 * j];
    #pragma unroll
    for (int j = 0; j < 4; j++) r1[j] = x1[lane + 32 * j];

    float z0[ELEMS], z1[ELEMS];
    #pragma unroll
    for (int j = 0; j < 4; j++) {
        z0[4 * j + 0] = r0[j].x; z0[4 * j + 1] = r0[j].y;
        z0[4 * j + 2] = r0[j].z; z0[4 * j + 3] = r0[j].w;
        z1[4 * j + 0] = r1[j].x; z1[4 * j + 1] = r1[j].y;
        z1[4 * j + 2] = r1[j].z; z1[4 * j + 3] = r1[j].w;
    }

    // Interleaved row-max chains.
    float m0 = z0[0], m1 = z1[0];
    #pragma unroll
    for (int i = 1; i < ELEMS; i++) {
        m0 = fmaxf(m0, z0[i]);
        m1 = fmaxf(m1, z1[i]);
    }
    warp_max2(m0, m1);
    const float thr0 = m0 - 1.0f;
    const float thr1 = m1 - 1.0f;

    // Compact candidates {z > thr} into 2 regs per lane per row.
    const float NEG_INF = __int_as_float(0xff800000);
    float a0 = NEG_INF, a1 = NEG_INF;   // row0 candidates
    float b0 = NEG_INF, b1 = NEG_INF;   // row1 candidates
    int nc0 = 0, nc1 = 0;
    #pragma unroll
    for (int i = 0; i < ELEMS; i++) {
        bool g0 = z0[i] > thr0;
        a1 = g0 ? a0 : a1;
        a0 = g0 ? z0[i] : a0;
        nc0 += g0 ? 1 : 0;
        bool g1 = z1[i] > thr1;
        b1 = g1 ? b0 : b1;
        b0 = g1 ? z1[i] : b0;
        nc1 += g1 ? 1 : 0;
    }

    const bool ovf0 = __ballot_sync(FULLM, nc0 > 2) != 0u;
    const bool ovf1 = __ballot_sync(FULLM, nc1 > 2) != 0u;

    float tau0, tau1;
    if (ovf0) tau0 = solve_full(z0, thr0);
    if (ovf1) tau1 = solve_full(z1, thr1);

    if (!(ovf0 && ovf1)) {
        // Seeds for both rows (interleaved sum ladders).
        float s0 = (a0 > thr0 ? a0 : 0.0f) + (a1 > thr0 ? a1 : 0.0f);
        float s1 = (b0 > thr1 ? b0 : 0.0f) + (b1 > thr1 ? b1 : 0.0f);
        warp_sum2(s0, s1);
        int c0 = __popc(__ballot_sync(FULLM, a0 > thr0)) +
                 __popc(__ballot_sync(FULLM, a1 > thr0));
        int c1 = __popc(__ballot_sync(FULLM, b0 > thr1)) +
                 __popc(__ballot_sync(FULLM, b1 > thr1));
        if (!ovf0) tau0 = __fdividef(s0 - 1.0f, (float)c0);
        if (!ovf1) tau1 = __fdividef(s1 - 1.0f, (float)c1);
        int cnt0 = c0, cnt1 = c1;
        bool done0 = ovf0, done1 = ovf1;

        #pragma unroll 1
        for (int it = 0; it < 24; it++) {
            bool A0 = a0 > tau0, A1 = a1 > tau0;
            bool B0 = b0 > tau1, B1 = b1 > tau1;
            float t0 = (A0 ? a0 : 0.0f) + (A1 ? a1 : 0.0f);
            float t1 = (B0 ? b0 : 0.0f) + (B1 ? b1 : 0.0f);
            warp_sum2(t0, t1);
            int k0 = __popc(__ballot_sync(FULLM, A0)) +
                     __popc(__ballot_sync(FULLM, A1));
            int k1 = __popc(__ballot_sync(FULLM, B0)) +
                     __popc(__ballot_sync(FULLM, B1));
            if (!done0) {
                if (k0 == cnt0) done0 = true;
                else { cnt0 = k0; tau0 = __fdividef(t0 - 1.0f, (float)k0); }
            }
            if (!done1) {
                if (k1 == cnt1) done1 = true;
                else { cnt1 = k1; tau1 = __fdividef(t1 - 1.0f, (float)k1); }
            }
            if (done0 && done1) break;
        }
    }

    // Epilogue: coalesced float4 stores for both rows.
    float4* __restrict__ o0 =
        reinterpret_cast<float4*>(out + (size_t)row0 * ROW_N);
    float4* __restrict__ o1 =
        reinterpret_cast<float4*>(out + (size_t)row1 * ROW_N);
    #pragma unroll
    for (int j = 0; j < 4; j++) {
        float4 v;
        v.x = fmaxf(z0[4 * j + 0] - tau0, 0.0f);
        v.y = fmaxf(z0[4 * j + 1] - tau0, 0.0f);
        v.z = fmaxf(z0[4 * j + 2] - tau0, 0.0f);
        v.w = fmaxf(z0[4 * j + 3] - tau0, 0.0f);
        o0[lane + 32 * j] = v;
        float4 w;
        w.x = fmaxf(z1[4 * j + 0] - tau1, 0.0f);
        w.y = fmaxf(z1[4 * j + 1] - tau1, 0.0f);
        w.z = fmaxf(z1[4 * j + 2] - tau1, 0.0f);
        w.w = fmaxf(z1[4 * j + 3] - tau1, 0.0f);
        o1[lane + 32 * j] = w;
    }
}

extern "C" void kernel_launch(void* const* d_in, const int* in_sizes, int n_in,
                              void* d_out, int out_size) {
    const float* x = (const float*)d_in[0];
    float* out = (float*)d_out;
    const int rows = in_sizes[0] / ROW_N;           // 65536
    const int pairs = (rows + 1) / 2;               // 32768
    const int blocks = (pairs + WARPS_PER_BLOCK - 1) / WARPS_PER_BLOCK;
    sparsemax_kernel<<<blocks, THREADS>>>(x, out, rows);
}